// round 3
// baseline (speedup 1.0000x reference)
#include <cuda_runtime.h>
#include <cuda_bf16.h>
#include <math.h>

#define BB 2
#define NQ 2048
#define NK 2048
#define DD 1024
#define HH 16
#define HDIM 64

// Scratch (allocation-free: __device__ globals)
__device__ float g_Q[(size_t)BB * NQ * DD];
__device__ float g_K[(size_t)BB * NK * DD];
__device__ float g_V[(size_t)BB * NK * DD];
__device__ float g_O[(size_t)BB * NQ * DD];

// ---------------------------------------------------------------------------
// Generic tiled GEMM: Y[m][n] = sum_k X[m][k] * W[n][k] + b[n]
// X: (M,K) row-major, W: (N,K) row-major. 64x64 block tile, 16 k-tile,
// 256 threads, 4x4 per-thread micro-tile.
// ---------------------------------------------------------------------------
__global__ void gemm_bias(const float* __restrict__ X, const float* __restrict__ W,
                          const float* __restrict__ b, float* __restrict__ Y,
                          int M, int N, int K) {
    __shared__ float Xs[64][17];
    __shared__ float Ws[64][17];
    int tid = threadIdx.x;
    int tx = tid % 16, ty = tid / 16;
    int row0 = blockIdx.y * 64, col0 = blockIdx.x * 64;

    float acc[4][4] = {};
    for (int kt = 0; kt < K; kt += 16) {
#pragma unroll
        for (int i = 0; i < 4; i++) {
            int idx = tid + i * 256;
            int r = idx >> 4, c = idx & 15;
            Xs[r][c] = X[(size_t)(row0 + r) * K + kt + c];
            Ws[r][c] = W[(size_t)(col0 + r) * K + kt + c];
        }
        __syncthreads();
#pragma unroll
        for (int kk = 0; kk < 16; kk++) {
            float xr[4], wr[4];
#pragma unroll
            for (int i = 0; i < 4; i++) xr[i] = Xs[ty * 4 + i][kk];
#pragma unroll
            for (int j = 0; j < 4; j++) wr[j] = Ws[tx * 4 + j][kk];
#pragma unroll
            for (int i = 0; i < 4; i++)
#pragma unroll
                for (int j = 0; j < 4; j++) acc[i][j] += xr[i] * wr[j];
        }
        __syncthreads();
    }
#pragma unroll
    for (int i = 0; i < 4; i++)
#pragma unroll
        for (int j = 0; j < 4; j++) {
            int r = row0 + ty * 4 + i, c = col0 + tx * 4 + j;
            Y[(size_t)r * N + c] = acc[i][j] + b[c];
        }
}

// ---------------------------------------------------------------------------
// xpos RoPE, in place on (B, N, H*HD). One thread per (row, head, pair).
// ---------------------------------------------------------------------------
__global__ void rope_kernel(float* __restrict__ X, const float* __restrict__ freqs,
                            int N, float scale_base, float sign) {
    int idx = blockIdx.x * blockDim.x + threadIdx.x;
    int total = BB * N * HH * (HDIM / 2);
    if (idx >= total) return;
    int p = idx & 31;             // pair index (HD/2 = 32)
    int h = (idx >> 5) & 15;      // head
    int row = idx >> 9;           // b*N + n
    int n = row % N;

    float t = (float)n;
    float fr = t * freqs[p];
    float c = cosf(fr), s = sinf(fr);
    float power = (t - (float)(N / 2)) / scale_base;
    float sv = (2.0f * (float)p + 0.4f * (float)HDIM) / (1.4f * (float)HDIM);
    float scale = powf(sv, power * sign);

    float* xp = X + (size_t)row * DD + h * HDIM + 2 * p;
    float x0 = xp[0], x1 = xp[1];
    xp[0] = (x0 * c - x1 * s) * scale;
    xp[1] = (x1 * c + x0 * s) * scale;
}

// ---------------------------------------------------------------------------
// Scores: S[b,h,q,k] = 0.125 * dot(Q[b,q,h,:], K[b,k,h,:])
// 64x64 output tile per block, k-dim = HD = 64 in 4 chunks of 16.
// ---------------------------------------------------------------------------
__global__ void scores_kernel(const float* __restrict__ Q, const float* __restrict__ Km,
                              float* __restrict__ attn) {
    int bh = blockIdx.z;
    int b = bh / HH, h = bh % HH;
    int q0 = blockIdx.y * 64, k0 = blockIdx.x * 64;
    const float* Qb = Q + (size_t)b * NQ * DD + h * HDIM;
    const float* Kb = Km + (size_t)b * NK * DD + h * HDIM;

    __shared__ float Qs[64][17];
    __shared__ float Ks[64][17];
    int tid = threadIdx.x;
    int tx = tid % 16, ty = tid / 16;
    float acc[4][4] = {};

    for (int kt = 0; kt < HDIM; kt += 16) {
#pragma unroll
        for (int i = 0; i < 4; i++) {
            int idx = tid + i * 256;
            int r = idx >> 4, c = idx & 15;
            Qs[r][c] = Qb[(size_t)(q0 + r) * DD + kt + c];
            Ks[r][c] = Kb[(size_t)(k0 + r) * DD + kt + c];
        }
        __syncthreads();
#pragma unroll
        for (int kk = 0; kk < 16; kk++) {
            float qr[4], kr[4];
#pragma unroll
            for (int i = 0; i < 4; i++) qr[i] = Qs[ty * 4 + i][kk];
#pragma unroll
            for (int j = 0; j < 4; j++) kr[j] = Ks[tx * 4 + j][kk];
#pragma unroll
            for (int i = 0; i < 4; i++)
#pragma unroll
                for (int j = 0; j < 4; j++) acc[i][j] += qr[i] * kr[j];
        }
        __syncthreads();
    }
    float* out = attn + (size_t)bh * NQ * NK;
    const float sc = 0.125f;  // HD^-0.5
#pragma unroll
    for (int i = 0; i < 4; i++)
#pragma unroll
        for (int j = 0; j < 4; j++)
            out[(size_t)(q0 + ty * 4 + i) * NK + (k0 + tx * 4 + j)] = acc[i][j] * sc;
}

// ---------------------------------------------------------------------------
// Row softmax in place. One block of 256 threads per row of length NK=2048.
// ---------------------------------------------------------------------------
__global__ void softmax_kernel(float* __restrict__ attn) {
    size_t row = blockIdx.x;
    float* p = attn + row * (size_t)NK;
    __shared__ float sm[NK];
    __shared__ float red[256];
    int t = threadIdx.x;

    float m = -1e30f;
    for (int i = t; i < NK; i += 256) {
        float v = p[i];
        sm[i] = v;
        m = fmaxf(m, v);
    }
    red[t] = m;
    __syncthreads();
    for (int s = 128; s > 0; s >>= 1) {
        if (t < s) red[t] = fmaxf(red[t], red[t + s]);
        __syncthreads();
    }
    m = red[0];
    __syncthreads();

    float sum = 0.0f;
    for (int i = t; i < NK; i += 256) {
        float e = expf(sm[i] - m);
        sm[i] = e;
        sum += e;
    }
    red[t] = sum;
    __syncthreads();
    for (int s = 128; s > 0; s >>= 1) {
        if (t < s) red[t] += red[t + s];
        __syncthreads();
    }
    float inv = 1.0f / red[0];
    for (int i = t; i < NK; i += 256) p[i] = sm[i] * inv;
}

// ---------------------------------------------------------------------------
// PV: O[b,q,h,:] = sum_k P[b,h,q,k] * V[b,k,h,:]
// Per (qtile, bh) block. M=2048, N=64 (one tile), K=2048 in chunks of 16.
// ---------------------------------------------------------------------------
__global__ void pv_kernel(const float* __restrict__ attn, const float* __restrict__ V,
                          float* __restrict__ O) {
    int bh = blockIdx.y;
    int b = bh / HH, h = bh % HH;
    int q0 = blockIdx.x * 64;
    const float* Pb = attn + (size_t)bh * NQ * NK;
    const float* Vb = V + (size_t)b * NK * DD + h * HDIM;

    __shared__ float Ps[64][17];
    __shared__ float Vs[16][65];
    int tid = threadIdx.x;
    int tx = tid % 16, ty = tid / 16;
    float acc[4][4] = {};

    for (int kt = 0; kt < NK; kt += 16) {
#pragma unroll
        for (int i = 0; i < 4; i++) {
            int idx = tid + i * 256;
            int r = idx >> 4, c = idx & 15;
            Ps[r][c] = Pb[(size_t)(q0 + r) * NK + kt + c];
            int vr = idx >> 6, vc = idx & 63;  // 16 rows x 64 cols
            Vs[vr][vc] = Vb[(size_t)(kt + vr) * DD + vc];
        }
        __syncthreads();
#pragma unroll
        for (int kk = 0; kk < 16; kk++) {
            float pr[4], vr[4];
#pragma unroll
            for (int i = 0; i < 4; i++) pr[i] = Ps[ty * 4 + i][kk];
#pragma unroll
            for (int j = 0; j < 4; j++) vr[j] = Vs[kk][tx * 4 + j];
#pragma unroll
            for (int i = 0; i < 4; i++)
#pragma unroll
                for (int j = 0; j < 4; j++) acc[i][j] += pr[i] * vr[j];
        }
        __syncthreads();
    }
#pragma unroll
    for (int i = 0; i < 4; i++)
#pragma unroll
        for (int j = 0; j < 4; j++)
            O[((size_t)b * NQ + q0 + ty * 4 + i) * DD + h * HDIM + tx * 4 + j] = acc[i][j];
}

// ---------------------------------------------------------------------------
extern "C" void kernel_launch(void* const* d_in, const int* in_sizes, int n_in,
                              void* d_out, int out_size) {
    const float* q_seq   = (const float*)d_in[0];
    const float* kv_seq  = (const float*)d_in[1];
    const float* Wq      = (const float*)d_in[2];
    const float* bq      = (const float*)d_in[3];
    const float* Wk      = (const float*)d_in[4];
    const float* bk      = (const float*)d_in[5];
    const float* Wv      = (const float*)d_in[6];
    const float* bv      = (const float*)d_in[7];
    const float* Wo      = (const float*)d_in[8];
    const float* bo      = (const float*)d_in[9];
    const float* freqs_q = (const float*)d_in[10];
    const float* freqs_kv= (const float*)d_in[11];

    float* out  = (float*)d_out;
    float* attn = out + (size_t)BB * NQ * DD;

    float *gQ, *gK, *gV, *gO;
    cudaGetSymbolAddress((void**)&gQ, g_Q);
    cudaGetSymbolAddress((void**)&gK, g_K);
    cudaGetSymbolAddress((void**)&gV, g_V);
    cudaGetSymbolAddress((void**)&gO, g_O);

    dim3 blk(256);
    dim3 gproj(DD / 64, (BB * NQ) / 64);

    gemm_bias<<<gproj, blk>>>(q_seq,  Wq, bq, gQ, BB * NQ, DD, DD);
    gemm_bias<<<gproj, blk>>>(kv_seq, Wk, bk, gK, BB * NK, DD, DD);
    gemm_bias<<<gproj, blk>>>(kv_seq, Wv, bv, gV, BB * NK, DD, DD);

    int nrope = BB * NQ * HH * (HDIM / 2);
    rope_kernel<<<nrope / 256, 256>>>(gQ, freqs_q,  NQ, (float)(2 * NQ),  1.0f);
    rope_kernel<<<nrope / 256, 256>>>(gK, freqs_kv, NK, (float)(2 * NK), -1.0f);

    scores_kernel<<<dim3(NK / 64, NQ / 64, BB * HH), blk>>>(gQ, gK, attn);
    softmax_kernel<<<BB * HH * NQ, 256>>>(attn);
    pv_kernel<<<dim3(NQ / 64, BB * HH), blk>>>(attn, gV, gO);

    gemm_bias<<<gproj, blk>>>(gO, Wo, bo, out, BB * NQ, DD, DD);
}

// round 4
// speedup vs baseline: 2.8615x; 2.8615x over previous
#include <cuda_runtime.h>
#include <cuda_bf16.h>
#include <math.h>
#include <stdint.h>

#define BB 2
#define NQ 2048
#define NK 2048
#define DD 1024
#define HH 16
#define HDIM 64

// Scratch (allocation-free: __device__ globals)
__device__ float g_Q[(size_t)BB * NQ * DD];
__device__ float g_K[(size_t)BB * NK * DD];
__device__ float g_V[(size_t)BB * NK * DD];
__device__ float g_O[(size_t)BB * NQ * DD];

// ---------------------------------------------------------------------------
// tf32 helpers
// ---------------------------------------------------------------------------
__device__ __forceinline__ uint32_t f2tf(float x) {
    uint32_t y;
    asm("cvt.rna.tf32.f32 %0, %1;" : "=r"(y) : "f"(x));
    return y;
}

// D = A(16x8, row) * B(8x8, col) + D, tf32 in, f32 acc
__device__ __forceinline__ void mma8(float c[4], const uint32_t a[4], const uint32_t b[2]) {
    asm volatile(
        "mma.sync.aligned.m16n8k8.row.col.f32.tf32.tf32.f32 "
        "{%0,%1,%2,%3}, {%4,%5,%6,%7}, {%8,%9}, {%0,%1,%2,%3};\n"
        : "+f"(c[0]), "+f"(c[1]), "+f"(c[2]), "+f"(c[3])
        : "r"(a[0]), "r"(a[1]), "r"(a[2]), "r"(a[3]), "r"(b[0]), "r"(b[1]));
}

// ---------------------------------------------------------------------------
// Tensor-core GEMM: Y[m][n] = sum_k X[m][k]*W[n][k] + b[n]
// Block tile 128x128, k-tile 32, 256 threads (8 warps, 2x4 warp grid,
// warp tile 64x32). tf32 mma, fp32 accumulate.
// ---------------------------------------------------------------------------
__global__ void __launch_bounds__(256)
gemm_bias_tc(const float* __restrict__ X, const float* __restrict__ W,
             const float* __restrict__ bias, float* __restrict__ Y,
             int M, int N, int K) {
    __shared__ uint32_t Xs[128][36];
    __shared__ uint32_t Ws[128][36];
    int tid = threadIdx.x;
    int warp = tid >> 5, lane = tid & 31;
    int g = lane >> 2, tig = lane & 3;
    int wm = warp >> 2, wn = warp & 3;     // 2 x 4 warps
    int row0 = blockIdx.y * 128, col0 = blockIdx.x * 128;

    float acc[4][4][4] = {};

    for (int kt = 0; kt < K; kt += 32) {
#pragma unroll
        for (int i = 0; i < 4; i++) {
            int idx = tid + i * 256;              // 0..1023
            int r = idx >> 3, c = (idx & 7) * 4;
            float4 xv = *(const float4*)(X + (size_t)(row0 + r) * K + kt + c);
            float4 wv = *(const float4*)(W + (size_t)(col0 + r) * K + kt + c);
            uint32_t* xp = &Xs[r][c];
            xp[0] = f2tf(xv.x); xp[1] = f2tf(xv.y); xp[2] = f2tf(xv.z); xp[3] = f2tf(xv.w);
            uint32_t* wp = &Ws[r][c];
            wp[0] = f2tf(wv.x); wp[1] = f2tf(wv.y); wp[2] = f2tf(wv.z); wp[3] = f2tf(wv.w);
        }
        __syncthreads();
#pragma unroll
        for (int ks = 0; ks < 4; ks++) {
            int k0 = ks * 8;
            uint32_t a[4][4], bf[4][2];
#pragma unroll
            for (int mi = 0; mi < 4; mi++) {
                int rb = wm * 64 + mi * 16 + g;
                a[mi][0] = Xs[rb][k0 + tig];
                a[mi][1] = Xs[rb + 8][k0 + tig];
                a[mi][2] = Xs[rb][k0 + tig + 4];
                a[mi][3] = Xs[rb + 8][k0 + tig + 4];
            }
#pragma unroll
            for (int ni = 0; ni < 4; ni++) {
                int cb = wn * 32 + ni * 8 + g;
                bf[ni][0] = Ws[cb][k0 + tig];
                bf[ni][1] = Ws[cb][k0 + tig + 4];
            }
#pragma unroll
            for (int mi = 0; mi < 4; mi++)
#pragma unroll
                for (int ni = 0; ni < 4; ni++)
                    mma8(acc[mi][ni], a[mi], bf[ni]);
        }
        __syncthreads();
    }
#pragma unroll
    for (int mi = 0; mi < 4; mi++) {
        int r = row0 + wm * 64 + mi * 16 + g;
#pragma unroll
        for (int ni = 0; ni < 4; ni++) {
            int c = col0 + wn * 32 + ni * 8 + tig * 2;
            float b0 = bias[c], b1 = bias[c + 1];
            *(float2*)(Y + (size_t)r * N + c) =
                make_float2(acc[mi][ni][0] + b0, acc[mi][ni][1] + b1);
            *(float2*)(Y + (size_t)(r + 8) * N + c) =
                make_float2(acc[mi][ni][2] + b0, acc[mi][ni][3] + b1);
        }
    }
}

// ---------------------------------------------------------------------------
// xpos RoPE, in place on (B, N, H*HD).
// ---------------------------------------------------------------------------
__global__ void rope_kernel(float* __restrict__ X, const float* __restrict__ freqs,
                            int N, float scale_base, float sign) {
    int idx = blockIdx.x * blockDim.x + threadIdx.x;
    int total = BB * N * HH * (HDIM / 2);
    if (idx >= total) return;
    int p = idx & 31;
    int h = (idx >> 5) & 15;
    int row = idx >> 9;
    int n = row % N;

    float t = (float)n;
    float fr = t * freqs[p];
    float c = cosf(fr), s = sinf(fr);
    float power = (t - (float)(N / 2)) / scale_base;
    float sv = (2.0f * (float)p + 0.4f * (float)HDIM) / (1.4f * (float)HDIM);
    float scale = powf(sv, power * sign);

    float* xp = X + (size_t)row * DD + h * HDIM + 2 * p;
    float x0 = xp[0], x1 = xp[1];
    xp[0] = (x0 * c - x1 * s) * scale;
    xp[1] = (x1 * c + x0 * s) * scale;
}

// ---------------------------------------------------------------------------
// Scores: S[b,h,q,k] = 0.125 * dot(Q[b,q,h,:], K[b,k,h,:])  (tensor cores)
// Block 128x128, depth = HD = 64 in two k-tiles of 32.
// ---------------------------------------------------------------------------
__global__ void __launch_bounds__(256)
scores_tc(const float* __restrict__ Q, const float* __restrict__ Km,
          float* __restrict__ attn) {
    __shared__ uint32_t Qs[128][36];
    __shared__ uint32_t Ks[128][36];
    int bh = blockIdx.z;
    int b = bh / HH, h = bh % HH;
    int q0 = blockIdx.y * 128, k0o = blockIdx.x * 128;
    const float* Qb = Q + (size_t)b * NQ * DD + h * HDIM;
    const float* Kb = Km + (size_t)b * NK * DD + h * HDIM;

    int tid = threadIdx.x;
    int warp = tid >> 5, lane = tid & 31;
    int g = lane >> 2, tig = lane & 3;
    int wm = warp >> 2, wn = warp & 3;
    float acc[4][4][4] = {};

    for (int kt = 0; kt < HDIM; kt += 32) {
#pragma unroll
        for (int i = 0; i < 4; i++) {
            int idx = tid + i * 256;
            int r = idx >> 3, c = (idx & 7) * 4;
            float4 qv = *(const float4*)(Qb + (size_t)(q0 + r) * DD + kt + c);
            float4 kv = *(const float4*)(Kb + (size_t)(k0o + r) * DD + kt + c);
            uint32_t* qp = &Qs[r][c];
            qp[0] = f2tf(qv.x); qp[1] = f2tf(qv.y); qp[2] = f2tf(qv.z); qp[3] = f2tf(qv.w);
            uint32_t* kp = &Ks[r][c];
            kp[0] = f2tf(kv.x); kp[1] = f2tf(kv.y); kp[2] = f2tf(kv.z); kp[3] = f2tf(kv.w);
        }
        __syncthreads();
#pragma unroll
        for (int ks = 0; ks < 4; ks++) {
            int k0 = ks * 8;
            uint32_t a[4][4], bf[4][2];
#pragma unroll
            for (int mi = 0; mi < 4; mi++) {
                int rb = wm * 64 + mi * 16 + g;
                a[mi][0] = Qs[rb][k0 + tig];
                a[mi][1] = Qs[rb + 8][k0 + tig];
                a[mi][2] = Qs[rb][k0 + tig + 4];
                a[mi][3] = Qs[rb + 8][k0 + tig + 4];
            }
#pragma unroll
            for (int ni = 0; ni < 4; ni++) {
                int cb = wn * 32 + ni * 8 + g;
                bf[ni][0] = Ks[cb][k0 + tig];
                bf[ni][1] = Ks[cb][k0 + tig + 4];
            }
#pragma unroll
            for (int mi = 0; mi < 4; mi++)
#pragma unroll
                for (int ni = 0; ni < 4; ni++)
                    mma8(acc[mi][ni], a[mi], bf[ni]);
        }
        __syncthreads();
    }
    float* out = attn + (size_t)bh * NQ * NK;
    const float sc = 0.125f;
#pragma unroll
    for (int mi = 0; mi < 4; mi++) {
        int r = q0 + wm * 64 + mi * 16 + g;
#pragma unroll
        for (int ni = 0; ni < 4; ni++) {
            int c = k0o + wn * 32 + ni * 8 + tig * 2;
            *(float2*)(out + (size_t)r * NK + c) =
                make_float2(acc[mi][ni][0] * sc, acc[mi][ni][1] * sc);
            *(float2*)(out + (size_t)(r + 8) * NK + c) =
                make_float2(acc[mi][ni][2] * sc, acc[mi][ni][3] * sc);
        }
    }
}

// ---------------------------------------------------------------------------
// Row softmax in place. One block of 256 threads per row of length NK=2048.
// ---------------------------------------------------------------------------
__global__ void softmax_kernel(float* __restrict__ attn) {
    size_t row = blockIdx.x;
    float* p = attn + row * (size_t)NK;
    __shared__ float sm[NK];
    __shared__ float red[256];
    int t = threadIdx.x;

    float m = -1e30f;
    for (int i = t; i < NK; i += 256) {
        float v = p[i];
        sm[i] = v;
        m = fmaxf(m, v);
    }
    red[t] = m;
    __syncthreads();
    for (int s = 128; s > 0; s >>= 1) {
        if (t < s) red[t] = fmaxf(red[t], red[t + s]);
        __syncthreads();
    }
    m = red[0];
    __syncthreads();

    float sum = 0.0f;
    for (int i = t; i < NK; i += 256) {
        float e = expf(sm[i] - m);
        sm[i] = e;
        sum += e;
    }
    red[t] = sum;
    __syncthreads();
    for (int s = 128; s > 0; s >>= 1) {
        if (t < s) red[t] += red[t + s];
        __syncthreads();
    }
    float inv = 1.0f / red[0];
    for (int i = t; i < NK; i += 256) p[i] = sm[i] * inv;
}

// ---------------------------------------------------------------------------
// PV: O[b,q,h,:] = sum_k P[b,h,q,k] * V[b,k,h,:]   (tensor cores)
// Block: 128 q x 64 n (full head). 8 warps in 4x2 grid, warp tile 32x32.
// ---------------------------------------------------------------------------
__global__ void __launch_bounds__(256)
pv_tc(const float* __restrict__ attn, const float* __restrict__ V,
      float* __restrict__ O) {
    __shared__ uint32_t Ps[128][36];
    __shared__ uint32_t Vs[32][72];
    int bh = blockIdx.y;
    int b = bh / HH, h = bh % HH;
    int q0 = blockIdx.x * 128;
    const float* Pb = attn + (size_t)bh * NQ * NK;
    const float* Vb = V + (size_t)b * NK * DD + h * HDIM;

    int tid = threadIdx.x;
    int warp = tid >> 5, lane = tid & 31;
    int g = lane >> 2, tig = lane & 3;
    int wm = warp >> 1, wn = warp & 1;   // 4 x 2 warps
    float acc[2][4][4] = {};

    for (int kt = 0; kt < NK; kt += 32) {
#pragma unroll
        for (int i = 0; i < 4; i++) {
            int idx = tid + i * 256;
            int r = idx >> 3, c = (idx & 7) * 4;
            float4 pv = *(const float4*)(Pb + (size_t)(q0 + r) * NK + kt + c);
            uint32_t* pp = &Ps[r][c];
            pp[0] = f2tf(pv.x); pp[1] = f2tf(pv.y); pp[2] = f2tf(pv.z); pp[3] = f2tf(pv.w);
        }
#pragma unroll
        for (int i = 0; i < 2; i++) {
            int idx = tid + i * 256;              // 0..511
            int r = idx >> 4, c = (idx & 15) * 4; // 32 rows x 64 cols
            float4 vv = *(const float4*)(Vb + (size_t)(kt + r) * DD + c);
            uint32_t* vp = &Vs[r][c];
            vp[0] = f2tf(vv.x); vp[1] = f2tf(vv.y); vp[2] = f2tf(vv.z); vp[3] = f2tf(vv.w);
        }
        __syncthreads();
#pragma unroll
        for (int ks = 0; ks < 4; ks++) {
            int k0 = ks * 8;
            uint32_t a[2][4], bf[4][2];
#pragma unroll
            for (int mi = 0; mi < 2; mi++) {
                int rb = wm * 32 + mi * 16 + g;
                a[mi][0] = Ps[rb][k0 + tig];
                a[mi][1] = Ps[rb + 8][k0 + tig];
                a[mi][2] = Ps[rb][k0 + tig + 4];
                a[mi][3] = Ps[rb + 8][k0 + tig + 4];
            }
#pragma unroll
            for (int ni = 0; ni < 4; ni++) {
                int nb = wn * 32 + ni * 8 + g;
                bf[ni][0] = Vs[k0 + tig][nb];
                bf[ni][1] = Vs[k0 + tig + 4][nb];
            }
#pragma unroll
            for (int mi = 0; mi < 2; mi++)
#pragma unroll
                for (int ni = 0; ni < 4; ni++)
                    mma8(acc[mi][ni], a[mi], bf[ni]);
        }
        __syncthreads();
    }
#pragma unroll
    for (int mi = 0; mi < 2; mi++) {
        int r = q0 + wm * 32 + mi * 16 + g;
#pragma unroll
        for (int ni = 0; ni < 4; ni++) {
            int c = wn * 32 + ni * 8 + tig * 2;
            float* o0 = O + ((size_t)b * NQ + r) * DD + h * HDIM + c;
            *(float2*)o0 = make_float2(acc[mi][ni][0], acc[mi][ni][1]);
            float* o1 = O + ((size_t)b * NQ + r + 8) * DD + h * HDIM + c;
            *(float2*)o1 = make_float2(acc[mi][ni][2], acc[mi][ni][3]);
        }
    }
}

// ---------------------------------------------------------------------------
extern "C" void kernel_launch(void* const* d_in, const int* in_sizes, int n_in,
                              void* d_out, int out_size) {
    const float* q_seq   = (const float*)d_in[0];
    const float* kv_seq  = (const float*)d_in[1];
    const float* Wq      = (const float*)d_in[2];
    const float* bq      = (const float*)d_in[3];
    const float* Wk      = (const float*)d_in[4];
    const float* bk      = (const float*)d_in[5];
    const float* Wv      = (const float*)d_in[6];
    const float* bv      = (const float*)d_in[7];
    const float* Wo      = (const float*)d_in[8];
    const float* bo      = (const float*)d_in[9];
    const float* freqs_q = (const float*)d_in[10];
    const float* freqs_kv= (const float*)d_in[11];

    float* out  = (float*)d_out;
    float* attn = out + (size_t)BB * NQ * DD;

    float *gQ, *gK, *gV, *gO;
    cudaGetSymbolAddress((void**)&gQ, g_Q);
    cudaGetSymbolAddress((void**)&gK, g_K);
    cudaGetSymbolAddress((void**)&gV, g_V);
    cudaGetSymbolAddress((void**)&gO, g_O);

    dim3 blk(256);
    dim3 gproj(DD / 128, (BB * NQ) / 128);

    gemm_bias_tc<<<gproj, blk>>>(q_seq,  Wq, bq, gQ, BB * NQ, DD, DD);
    gemm_bias_tc<<<gproj, blk>>>(kv_seq, Wk, bk, gK, BB * NK, DD, DD);
    gemm_bias_tc<<<gproj, blk>>>(kv_seq, Wv, bv, gV, BB * NK, DD, DD);

    int nrope = BB * NQ * HH * (HDIM / 2);
    rope_kernel<<<nrope / 256, 256>>>(gQ, freqs_q,  NQ, (float)(2 * NQ),  1.0f);
    rope_kernel<<<nrope / 256, 256>>>(gK, freqs_kv, NK, (float)(2 * NK), -1.0f);

    scores_tc<<<dim3(NK / 128, NQ / 128, BB * HH), blk>>>(gQ, gK, attn);
    softmax_kernel<<<BB * HH * NQ, 256>>>(attn);
    pv_tc<<<dim3(NQ / 128, BB * HH), blk>>>(attn, gV, gO);

    gemm_bias_tc<<<gproj, blk>>>(gO, Wo, bo, out, BB * NQ, DD, DD);
}

// round 5
// speedup vs baseline: 2.9176x; 1.0196x over previous
#include <cuda_runtime.h>
#include <cuda_bf16.h>
#include <math.h>
#include <stdint.h>

#define BB 2
#define NQ 2048
#define NK 2048
#define DD 1024
#define HH 16
#define HDIM 64

// Scratch (allocation-free: __device__ globals)
__device__ float g_Q[(size_t)BB * NQ * DD];
__device__ float g_K[(size_t)BB * NK * DD];
__device__ float g_V[(size_t)BB * NK * DD];
__device__ float g_O[(size_t)BB * NQ * DD];

// ---------------------------------------------------------------------------
// tf32 helpers
// ---------------------------------------------------------------------------
__device__ __forceinline__ uint32_t f2tf(float x) {
    uint32_t y;
    asm("cvt.rna.tf32.f32 %0, %1;" : "=r"(y) : "f"(x));
    return y;
}

// D = A(16x8, row) * B(8x8, col) + D, tf32 in, f32 acc
__device__ __forceinline__ void mma8(float c[4], const uint32_t a[4], const uint32_t b[2]) {
    asm volatile(
        "mma.sync.aligned.m16n8k8.row.col.f32.tf32.tf32.f32 "
        "{%0,%1,%2,%3}, {%4,%5,%6,%7}, {%8,%9}, {%0,%1,%2,%3};\n"
        : "+f"(c[0]), "+f"(c[1]), "+f"(c[2]), "+f"(c[3])
        : "r"(a[0]), "r"(a[1]), "r"(a[2]), "r"(a[3]), "r"(b[0]), "r"(b[1]));
}

// ---------------------------------------------------------------------------
// Tensor-core GEMM: Y[m][n] = sum_k X[m][k]*W[n][k] + b[n]
// Block tile 128x128, k-tile 32, 256 threads (8 warps, 2x4 warp grid,
// warp tile 64x32). tf32 mma, fp32 accumulate.
// ---------------------------------------------------------------------------
__global__ void __launch_bounds__(256)
gemm_bias_tc(const float* __restrict__ X, const float* __restrict__ W,
             const float* __restrict__ bias, float* __restrict__ Y,
             int M, int N, int K) {
    __shared__ uint32_t Xs[128][36];
    __shared__ uint32_t Ws[128][36];
    int tid = threadIdx.x;
    int warp = tid >> 5, lane = tid & 31;
    int g = lane >> 2, tig = lane & 3;
    int wm = warp >> 2, wn = warp & 3;     // 2 x 4 warps
    int row0 = blockIdx.y * 128, col0 = blockIdx.x * 128;

    float acc[4][4][4] = {};

    for (int kt = 0; kt < K; kt += 32) {
#pragma unroll
        for (int i = 0; i < 4; i++) {
            int idx = tid + i * 256;              // 0..1023
            int r = idx >> 3, c = (idx & 7) * 4;
            float4 xv = *(const float4*)(X + (size_t)(row0 + r) * K + kt + c);
            float4 wv = *(const float4*)(W + (size_t)(col0 + r) * K + kt + c);
            uint32_t* xp = &Xs[r][c];
            xp[0] = f2tf(xv.x); xp[1] = f2tf(xv.y); xp[2] = f2tf(xv.z); xp[3] = f2tf(xv.w);
            uint32_t* wp = &Ws[r][c];
            wp[0] = f2tf(wv.x); wp[1] = f2tf(wv.y); wp[2] = f2tf(wv.z); wp[3] = f2tf(wv.w);
        }
        __syncthreads();
#pragma unroll
        for (int ks = 0; ks < 4; ks++) {
            int k0 = ks * 8;
            uint32_t a[4][4], bf[4][2];
#pragma unroll
            for (int mi = 0; mi < 4; mi++) {
                int rb = wm * 64 + mi * 16 + g;
                a[mi][0] = Xs[rb][k0 + tig];
                a[mi][1] = Xs[rb + 8][k0 + tig];
                a[mi][2] = Xs[rb][k0 + tig + 4];
                a[mi][3] = Xs[rb + 8][k0 + tig + 4];
            }
#pragma unroll
            for (int ni = 0; ni < 4; ni++) {
                int cb = wn * 32 + ni * 8 + g;
                bf[ni][0] = Ws[cb][k0 + tig];
                bf[ni][1] = Ws[cb][k0 + tig + 4];
            }
#pragma unroll
            for (int mi = 0; mi < 4; mi++)
#pragma unroll
                for (int ni = 0; ni < 4; ni++)
                    mma8(acc[mi][ni], a[mi], bf[ni]);
        }
        __syncthreads();
    }
#pragma unroll
    for (int mi = 0; mi < 4; mi++) {
        int r = row0 + wm * 64 + mi * 16 + g;
#pragma unroll
        for (int ni = 0; ni < 4; ni++) {
            int c = col0 + wn * 32 + ni * 8 + tig * 2;
            float b0 = bias[c], b1 = bias[c + 1];
            *(float2*)(Y + (size_t)r * N + c) =
                make_float2(acc[mi][ni][0] + b0, acc[mi][ni][1] + b1);
            *(float2*)(Y + (size_t)(r + 8) * N + c) =
                make_float2(acc[mi][ni][2] + b0, acc[mi][ni][3] + b1);
        }
    }
}

// ---------------------------------------------------------------------------
// xpos RoPE, in place on (B, N, H*HD).
// ---------------------------------------------------------------------------
__global__ void rope_kernel(float* __restrict__ X, const float* __restrict__ freqs,
                            int N, float scale_base, float sign) {
    int idx = blockIdx.x * blockDim.x + threadIdx.x;
    int total = BB * N * HH * (HDIM / 2);
    if (idx >= total) return;
    int p = idx & 31;
    int h = (idx >> 5) & 15;
    int row = idx >> 9;
    int n = row % N;

    float t = (float)n;
    float fr = t * freqs[p];
    float c = cosf(fr), s = sinf(fr);
    float power = (t - (float)(N / 2)) / scale_base;
    float sv = (2.0f * (float)p + 0.4f * (float)HDIM) / (1.4f * (float)HDIM);
    float scale = powf(sv, power * sign);

    float* xp = X + (size_t)row * DD + h * HDIM + 2 * p;
    float x0 = xp[0], x1 = xp[1];
    xp[0] = (x0 * c - x1 * s) * scale;
    xp[1] = (x1 * c + x0 * s) * scale;
}

// ---------------------------------------------------------------------------
// Scores: S[b,h,q,k] = 0.125 * dot(Q[b,q,h,:], K[b,k,h,:])  (tensor cores)
// Block 128x128, depth = HD = 64 in two k-tiles of 32.
// ---------------------------------------------------------------------------
__global__ void __launch_bounds__(256)
scores_tc(const float* __restrict__ Q, const float* __restrict__ Km,
          float* __restrict__ attn) {
    __shared__ uint32_t Qs[128][36];
    __shared__ uint32_t Ks[128][36];
    int bh = blockIdx.z;
    int b = bh / HH, h = bh % HH;
    int q0 = blockIdx.y * 128, k0o = blockIdx.x * 128;
    const float* Qb = Q + (size_t)b * NQ * DD + h * HDIM;
    const float* Kb = Km + (size_t)b * NK * DD + h * HDIM;

    int tid = threadIdx.x;
    int warp = tid >> 5, lane = tid & 31;
    int g = lane >> 2, tig = lane & 3;
    int wm = warp >> 2, wn = warp & 3;
    float acc[4][4][4] = {};

    for (int kt = 0; kt < HDIM; kt += 32) {
#pragma unroll
        for (int i = 0; i < 4; i++) {
            int idx = tid + i * 256;
            int r = idx >> 3, c = (idx & 7) * 4;
            float4 qv = *(const float4*)(Qb + (size_t)(q0 + r) * DD + kt + c);
            float4 kv = *(const float4*)(Kb + (size_t)(k0o + r) * DD + kt + c);
            uint32_t* qp = &Qs[r][c];
            qp[0] = f2tf(qv.x); qp[1] = f2tf(qv.y); qp[2] = f2tf(qv.z); qp[3] = f2tf(qv.w);
            uint32_t* kp = &Ks[r][c];
            kp[0] = f2tf(kv.x); kp[1] = f2tf(kv.y); kp[2] = f2tf(kv.z); kp[3] = f2tf(kv.w);
        }
        __syncthreads();
#pragma unroll
        for (int ks = 0; ks < 4; ks++) {
            int k0 = ks * 8;
            uint32_t a[4][4], bf[4][2];
#pragma unroll
            for (int mi = 0; mi < 4; mi++) {
                int rb = wm * 64 + mi * 16 + g;
                a[mi][0] = Qs[rb][k0 + tig];
                a[mi][1] = Qs[rb + 8][k0 + tig];
                a[mi][2] = Qs[rb][k0 + tig + 4];
                a[mi][3] = Qs[rb + 8][k0 + tig + 4];
            }
#pragma unroll
            for (int ni = 0; ni < 4; ni++) {
                int cb = wn * 32 + ni * 8 + g;
                bf[ni][0] = Ks[cb][k0 + tig];
                bf[ni][1] = Ks[cb][k0 + tig + 4];
            }
#pragma unroll
            for (int mi = 0; mi < 4; mi++)
#pragma unroll
                for (int ni = 0; ni < 4; ni++)
                    mma8(acc[mi][ni], a[mi], bf[ni]);
        }
        __syncthreads();
    }
    float* out = attn + (size_t)bh * NQ * NK;
    const float sc = 0.125f;
#pragma unroll
    for (int mi = 0; mi < 4; mi++) {
        int r = q0 + wm * 64 + mi * 16 + g;
#pragma unroll
        for (int ni = 0; ni < 4; ni++) {
            int c = k0o + wn * 32 + ni * 8 + tig * 2;
            *(float2*)(out + (size_t)r * NK + c) =
                make_float2(acc[mi][ni][0] * sc, acc[mi][ni][1] * sc);
            *(float2*)(out + (size_t)(r + 8) * NK + c) =
                make_float2(acc[mi][ni][2] * sc, acc[mi][ni][3] * sc);
        }
    }
}

// ---------------------------------------------------------------------------
// Row softmax in place. One block of 256 threads per row of length NK=2048.
// ---------------------------------------------------------------------------
__global__ void softmax_kernel(float* __restrict__ attn) {
    size_t row = blockIdx.x;
    float* p = attn + row * (size_t)NK;
    __shared__ float sm[NK];
    __shared__ float red[256];
    int t = threadIdx.x;

    float m = -1e30f;
    for (int i = t; i < NK; i += 256) {
        float v = p[i];
        sm[i] = v;
        m = fmaxf(m, v);
    }
    red[t] = m;
    __syncthreads();
    for (int s = 128; s > 0; s >>= 1) {
        if (t < s) red[t] = fmaxf(red[t], red[t + s]);
        __syncthreads();
    }
    m = red[0];
    __syncthreads();

    float sum = 0.0f;
    for (int i = t; i < NK; i += 256) {
        float e = expf(sm[i] - m);
        sm[i] = e;
        sum += e;
    }
    red[t] = sum;
    __syncthreads();
    for (int s = 128; s > 0; s >>= 1) {
        if (t < s) red[t] += red[t + s];
        __syncthreads();
    }
    float inv = 1.0f / red[0];
    for (int i = t; i < NK; i += 256) p[i] = sm[i] * inv;
}

// ---------------------------------------------------------------------------
// PV: O[b,q,h,:] = sum_k P[b,h,q,k] * V[b,k,h,:]   (tensor cores)
// Block: 128 q x 64 n (full head). 8 warps in 4x2 grid, warp tile 32x32.
// ---------------------------------------------------------------------------
__global__ void __launch_bounds__(256)
pv_tc(const float* __restrict__ attn, const float* __restrict__ V,
      float* __restrict__ O) {
    __shared__ uint32_t Ps[128][36];
    __shared__ uint32_t Vs[32][72];
    int bh = blockIdx.y;
    int b = bh / HH, h = bh % HH;
    int q0 = blockIdx.x * 128;
    const float* Pb = attn + (size_t)bh * NQ * NK;
    const float* Vb = V + (size_t)b * NK * DD + h * HDIM;

    int tid = threadIdx.x;
    int warp = tid >> 5, lane = tid & 31;
    int g = lane >> 2, tig = lane & 3;
    int wm = warp >> 1, wn = warp & 1;   // 4 x 2 warps
    float acc[2][4][4] = {};

    for (int kt = 0; kt < NK; kt += 32) {
#pragma unroll
        for (int i = 0; i < 4; i++) {
            int idx = tid + i * 256;
            int r = idx >> 3, c = (idx & 7) * 4;
            float4 pv = *(const float4*)(Pb + (size_t)(q0 + r) * NK + kt + c);
            uint32_t* pp = &Ps[r][c];
            pp[0] = f2tf(pv.x); pp[1] = f2tf(pv.y); pp[2] = f2tf(pv.z); pp[3] = f2tf(pv.w);
        }
#pragma unroll
        for (int i = 0; i < 2; i++) {
            int idx = tid + i * 256;              // 0..511
            int r = idx >> 4, c = (idx & 15) * 4; // 32 rows x 64 cols
            float4 vv = *(const float4*)(Vb + (size_t)(kt + r) * DD + c);
            uint32_t* vp = &Vs[r][c];
            vp[0] = f2tf(vv.x); vp[1] = f2tf(vv.y); vp[2] = f2tf(vv.z); vp[3] = f2tf(vv.w);
        }
        __syncthreads();
#pragma unroll
        for (int ks = 0; ks < 4; ks++) {
            int k0 = ks * 8;
            uint32_t a[2][4], bf[4][2];
#pragma unroll
            for (int mi = 0; mi < 2; mi++) {
                int rb = wm * 32 + mi * 16 + g;
                a[mi][0] = Ps[rb][k0 + tig];
                a[mi][1] = Ps[rb + 8][k0 + tig];
                a[mi][2] = Ps[rb][k0 + tig + 4];
                a[mi][3] = Ps[rb + 8][k0 + tig + 4];
            }
#pragma unroll
            for (int ni = 0; ni < 4; ni++) {
                int nb = wn * 32 + ni * 8 + g;
                bf[ni][0] = Vs[k0 + tig][nb];
                bf[ni][1] = Vs[k0 + tig + 4][nb];
            }
#pragma unroll
            for (int mi = 0; mi < 2; mi++)
#pragma unroll
                for (int ni = 0; ni < 4; ni++)
                    mma8(acc[mi][ni], a[mi], bf[ni]);
        }
        __syncthreads();
    }
#pragma unroll
    for (int mi = 0; mi < 2; mi++) {
        int r = q0 + wm * 32 + mi * 16 + g;
#pragma unroll
        for (int ni = 0; ni < 4; ni++) {
            int c = wn * 32 + ni * 8 + tig * 2;
            float* o0 = O + ((size_t)b * NQ + r) * DD + h * HDIM + c;
            *(float2*)o0 = make_float2(acc[mi][ni][0], acc[mi][ni][1]);
            float* o1 = O + ((size_t)b * NQ + r + 8) * DD + h * HDIM + c;
            *(float2*)o1 = make_float2(acc[mi][ni][2], acc[mi][ni][3]);
        }
    }
}

// ---------------------------------------------------------------------------
extern "C" void kernel_launch(void* const* d_in, const int* in_sizes, int n_in,
                              void* d_out, int out_size) {
    const float* q_seq   = (const float*)d_in[0];
    const float* kv_seq  = (const float*)d_in[1];
    const float* Wq      = (const float*)d_in[2];
    const float* bq      = (const float*)d_in[3];
    const float* Wk      = (const float*)d_in[4];
    const float* bk      = (const float*)d_in[5];
    const float* Wv      = (const float*)d_in[6];
    const float* bv      = (const float*)d_in[7];
    const float* Wo      = (const float*)d_in[8];
    const float* bo      = (const float*)d_in[9];
    const float* freqs_q = (const float*)d_in[10];
    const float* freqs_kv= (const float*)d_in[11];

    float* out  = (float*)d_out;
    float* attn = out + (size_t)BB * NQ * DD;

    float *gQ, *gK, *gV, *gO;
    cudaGetSymbolAddress((void**)&gQ, g_Q);
    cudaGetSymbolAddress((void**)&gK, g_K);
    cudaGetSymbolAddress((void**)&gV, g_V);
    cudaGetSymbolAddress((void**)&gO, g_O);

    dim3 blk(256);
    dim3 gproj(DD / 128, (BB * NQ) / 128);

    gemm_bias_tc<<<gproj, blk>>>(q_seq,  Wq, bq, gQ, BB * NQ, DD, DD);
    gemm_bias_tc<<<gproj, blk>>>(kv_seq, Wk, bk, gK, BB * NK, DD, DD);
    gemm_bias_tc<<<gproj, blk>>>(kv_seq, Wv, bv, gV, BB * NK, DD, DD);

    int nrope = BB * NQ * HH * (HDIM / 2);
    rope_kernel<<<nrope / 256, 256>>>(gQ, freqs_q,  NQ, (float)(2 * NQ),  1.0f);
    rope_kernel<<<nrope / 256, 256>>>(gK, freqs_kv, NK, (float)(2 * NK), -1.0f);

    scores_tc<<<dim3(NK / 128, NQ / 128, BB * HH), blk>>>(gQ, gK, attn);
    softmax_kernel<<<BB * HH * NQ, 256>>>(attn);
    pv_tc<<<dim3(NQ / 128, BB * HH), blk>>>(attn, gV, gO);

    gemm_bias_tc<<<gproj, blk>>>(gO, Wo, bo, out, BB * NQ, DD, DD);
}

// round 6
// speedup vs baseline: 3.6843x; 1.2628x over previous
#include <cuda_runtime.h>
#include <cuda_bf16.h>
#include <math.h>
#include <stdint.h>

#define BB 2
#define NQ 2048
#define NK 2048
#define DD 1024
#define HH 16
#define HDIM 64

// Scratch (allocation-free: __device__ globals)
__device__ float g_Q[(size_t)BB * NQ * DD];
__device__ float g_K[(size_t)BB * NK * DD];
__device__ float g_V[(size_t)BB * NK * DD];
__device__ float g_O[(size_t)BB * NQ * DD];

// ---------------------------------------------------------------------------
// tf32 helpers
// ---------------------------------------------------------------------------
__device__ __forceinline__ uint32_t f2tf(float x) {
    uint32_t y;
    asm("cvt.rna.tf32.f32 %0, %1;" : "=r"(y) : "f"(x));
    return y;
}

// D = A(16x8, row) * B(8x8, col) + D, tf32 in, f32 acc
__device__ __forceinline__ void mma8(float c[4], const uint32_t a[4], const uint32_t b[2]) {
    asm volatile(
        "mma.sync.aligned.m16n8k8.row.col.f32.tf32.tf32.f32 "
        "{%0,%1,%2,%3}, {%4,%5,%6,%7}, {%8,%9}, {%0,%1,%2,%3};\n"
        : "+f"(c[0]), "+f"(c[1]), "+f"(c[2]), "+f"(c[3])
        : "r"(a[0]), "r"(a[1]), "r"(a[2]), "r"(a[3]), "r"(b[0]), "r"(b[1]));
}

// ---------------------------------------------------------------------------
// Tensor-core GEMM: Y[m][n] = sum_k X[m][k]*W[n][k] + b[n]
// Block tile 128x128, k-tile 32, 256 threads (8 warps, 2x4 warp grid,
// warp tile 64x32). tf32 mma, fp32 accumulate.
// ---------------------------------------------------------------------------
__global__ void __launch_bounds__(256)
gemm_bias_tc(const float* __restrict__ X, const float* __restrict__ W,
             const float* __restrict__ bias, float* __restrict__ Y,
             int M, int N, int K) {
    __shared__ uint32_t Xs[128][36];
    __shared__ uint32_t Ws[128][36];
    int tid = threadIdx.x;
    int warp = tid >> 5, lane = tid & 31;
    int g = lane >> 2, tig = lane & 3;
    int wm = warp >> 2, wn = warp & 3;     // 2 x 4 warps
    int row0 = blockIdx.y * 128, col0 = blockIdx.x * 128;

    float acc[4][4][4] = {};

    for (int kt = 0; kt < K; kt += 32) {
#pragma unroll
        for (int i = 0; i < 4; i++) {
            int idx = tid + i * 256;              // 0..1023
            int r = idx >> 3, c = (idx & 7) * 4;
            float4 xv = *(const float4*)(X + (size_t)(row0 + r) * K + kt + c);
            float4 wv = *(const float4*)(W + (size_t)(col0 + r) * K + kt + c);
            uint32_t* xp = &Xs[r][c];
            xp[0] = f2tf(xv.x); xp[1] = f2tf(xv.y); xp[2] = f2tf(xv.z); xp[3] = f2tf(xv.w);
            uint32_t* wp = &Ws[r][c];
            wp[0] = f2tf(wv.x); wp[1] = f2tf(wv.y); wp[2] = f2tf(wv.z); wp[3] = f2tf(wv.w);
        }
        __syncthreads();
#pragma unroll
        for (int ks = 0; ks < 4; ks++) {
            int k0 = ks * 8;
            uint32_t a[4][4], bf[4][2];
#pragma unroll
            for (int mi = 0; mi < 4; mi++) {
                int rb = wm * 64 + mi * 16 + g;
                a[mi][0] = Xs[rb][k0 + tig];
                a[mi][1] = Xs[rb + 8][k0 + tig];
                a[mi][2] = Xs[rb][k0 + tig + 4];
                a[mi][3] = Xs[rb + 8][k0 + tig + 4];
            }
#pragma unroll
            for (int ni = 0; ni < 4; ni++) {
                int cb = wn * 32 + ni * 8 + g;
                bf[ni][0] = Ws[cb][k0 + tig];
                bf[ni][1] = Ws[cb][k0 + tig + 4];
            }
#pragma unroll
            for (int mi = 0; mi < 4; mi++)
#pragma unroll
                for (int ni = 0; ni < 4; ni++)
                    mma8(acc[mi][ni], a[mi], bf[ni]);
        }
        __syncthreads();
    }
#pragma unroll
    for (int mi = 0; mi < 4; mi++) {
        int r = row0 + wm * 64 + mi * 16 + g;
#pragma unroll
        for (int ni = 0; ni < 4; ni++) {
            int c = col0 + wn * 32 + ni * 8 + tig * 2;
            float b0 = bias[c], b1 = bias[c + 1];
            *(float2*)(Y + (size_t)r * N + c) =
                make_float2(acc[mi][ni][0] + b0, acc[mi][ni][1] + b1);
            *(float2*)(Y + (size_t)(r + 8) * N + c) =
                make_float2(acc[mi][ni][2] + b0, acc[mi][ni][3] + b1);
        }
    }
}

// ---------------------------------------------------------------------------
// xpos RoPE, in place on (B, N, H*HD).
// ---------------------------------------------------------------------------
__global__ void rope_kernel(float* __restrict__ X, const float* __restrict__ freqs,
                            int N, float scale_base, float sign) {
    int idx = blockIdx.x * blockDim.x + threadIdx.x;
    int total = BB * N * HH * (HDIM / 2);
    if (idx >= total) return;
    int p = idx & 31;
    int h = (idx >> 5) & 15;
    int row = idx >> 9;
    int n = row % N;

    float t = (float)n;
    float fr = t * freqs[p];
    float c = cosf(fr), s = sinf(fr);
    float power = (t - (float)(N / 2)) / scale_base;
    float sv = (2.0f * (float)p + 0.4f * (float)HDIM) / (1.4f * (float)HDIM);
    float scale = powf(sv, power * sign);

    float* xp = X + (size_t)row * DD + h * HDIM + 2 * p;
    float x0 = xp[0], x1 = xp[1];
    xp[0] = (x0 * c - x1 * s) * scale;
    xp[1] = (x1 * c + x0 * s) * scale;
}

// ---------------------------------------------------------------------------
// Fused attention: per (bh, 128-q-tile) block.
//   Pass 1: S = (0.125*Q)K^T streamed over 16 k-tiles of 128; row sums of
//           exp(S) accumulated (no max subtraction; scores are O(10)).
//   Pass 2: recompute S (bit-identical), P = exp(S)/rowsum written once to
//           attn output; P staged in smem (tf32) and fed to P*V tensor-core
//           MMA; O accumulated in registers, written at the end.
// 256 threads. S uses 2x4 warp grid (64x32 warp tiles); PV uses 4x2 (32x32).
// ---------------------------------------------------------------------------
#define QPAD 68
#define PPAD 132
#define SMEM_WORDS (3 * 128 * QPAD + 128 * PPAD + 4 * 128 + 128)
#define SMEM_BYTES (SMEM_WORDS * 4)

extern __shared__ uint32_t smbuf[];

__global__ void __launch_bounds__(256, 1)
attn_fused(const float* __restrict__ Q, const float* __restrict__ Kg,
           const float* __restrict__ Vg, float* __restrict__ attn,
           float* __restrict__ O) {
    uint32_t* Qs = smbuf;                       // [128][QPAD]
    uint32_t* Ks = Qs + 128 * QPAD;             // [128][QPAD]
    uint32_t* Vs = Ks + 128 * QPAD;             // [128][QPAD] rows=k, cols=d
    uint32_t* Ps = Vs + 128 * QPAD;             // [128][PPAD]
    float* part = (float*)(Ps + 128 * PPAD);    // [4][128] per-wn row partials
    float* rinv = part + 4 * 128;               // [128]

    int bh = blockIdx.y;
    int b = bh / HH, h = bh % HH;
    int q0 = blockIdx.x * 128;
    const float* Qb = Q + (size_t)b * NQ * DD + h * HDIM;
    const float* Kb = Kg + (size_t)b * NK * DD + h * HDIM;
    const float* Vb = Vg + (size_t)b * NK * DD + h * HDIM;
    float* outP = attn + (size_t)bh * NQ * NK;

    int tid = threadIdx.x;
    int warp = tid >> 5, lane = tid & 31;
    int g = lane >> 2, tig = lane & 3;
    int wm = warp >> 2, wn = warp & 3;       // 2x4 (S)
    int wm2 = warp >> 1, wn2 = warp & 1;     // 4x2 (PV)

    // Load Q tile once, pre-scaled by HD^-0.5 = 0.125 (exact power of 2).
#pragma unroll
    for (int i = 0; i < 8; i++) {
        int idx = tid + i * 256;             // 0..2047 float4s
        int r = idx >> 4, c = (idx & 15) * 4;
        float4 v = *(const float4*)(Qb + (size_t)(q0 + r) * DD + c);
        uint32_t* p = Qs + r * QPAD + c;
        p[0] = f2tf(v.x * 0.125f); p[1] = f2tf(v.y * 0.125f);
        p[2] = f2tf(v.z * 0.125f); p[3] = f2tf(v.w * 0.125f);
    }
    __syncthreads();

    // ---------------- Pass 1: row sums of exp(S) ----------------
    float rs[8] = {};   // rows wm*64 + mi*16 + g (+8): index mi*2 + {0,1}
    for (int kt = 0; kt < 16; kt++) {
#pragma unroll
        for (int i = 0; i < 8; i++) {
            int idx = tid + i * 256;
            int r = idx >> 4, c = (idx & 15) * 4;
            float4 v = *(const float4*)(Kb + (size_t)(kt * 128 + r) * DD + c);
            uint32_t* p = Ks + r * QPAD + c;
            p[0] = f2tf(v.x); p[1] = f2tf(v.y); p[2] = f2tf(v.z); p[3] = f2tf(v.w);
        }
        __syncthreads();
        float acc[4][4][4] = {};
#pragma unroll
        for (int ks = 0; ks < 8; ks++) {
            int k0 = ks * 8;
            uint32_t a[4][4], bf[4][2];
#pragma unroll
            for (int mi = 0; mi < 4; mi++) {
                int rb = wm * 64 + mi * 16 + g;
                a[mi][0] = Qs[rb * QPAD + k0 + tig];
                a[mi][1] = Qs[(rb + 8) * QPAD + k0 + tig];
                a[mi][2] = Qs[rb * QPAD + k0 + tig + 4];
                a[mi][3] = Qs[(rb + 8) * QPAD + k0 + tig + 4];
            }
#pragma unroll
            for (int ni = 0; ni < 4; ni++) {
                int cb = wn * 32 + ni * 8 + g;
                bf[ni][0] = Ks[cb * QPAD + k0 + tig];
                bf[ni][1] = Ks[cb * QPAD + k0 + tig + 4];
            }
#pragma unroll
            for (int mi = 0; mi < 4; mi++)
#pragma unroll
                for (int ni = 0; ni < 4; ni++)
                    mma8(acc[mi][ni], a[mi], bf[ni]);
        }
#pragma unroll
        for (int mi = 0; mi < 4; mi++)
#pragma unroll
            for (int ni = 0; ni < 4; ni++) {
                rs[mi * 2 + 0] += __expf(acc[mi][ni][0]) + __expf(acc[mi][ni][1]);
                rs[mi * 2 + 1] += __expf(acc[mi][ni][2]) + __expf(acc[mi][ni][3]);
            }
        __syncthreads();
    }
    // Deterministic cross-warp row-sum reduction.
#pragma unroll
    for (int j = 0; j < 8; j++) {
        float v = rs[j];
        v += __shfl_xor_sync(0xffffffffu, v, 1);
        v += __shfl_xor_sync(0xffffffffu, v, 2);
        if (tig == 0)
            part[wn * 128 + wm * 64 + (j >> 1) * 16 + g + (j & 1) * 8] = v;
    }
    __syncthreads();
    if (tid < 128)
        rinv[tid] = 1.0f / (part[tid] + part[128 + tid] + part[256 + tid] + part[384 + tid]);
    __syncthreads();

    // ---------------- Pass 2: P out + P*V ----------------
    float acc_o[2][4][4] = {};
    for (int kt = 0; kt < 16; kt++) {
#pragma unroll
        for (int i = 0; i < 8; i++) {
            int idx = tid + i * 256;
            int r = idx >> 4, c = (idx & 15) * 4;
            float4 kv = *(const float4*)(Kb + (size_t)(kt * 128 + r) * DD + c);
            uint32_t* kp = Ks + r * QPAD + c;
            kp[0] = f2tf(kv.x); kp[1] = f2tf(kv.y); kp[2] = f2tf(kv.z); kp[3] = f2tf(kv.w);
            float4 vv = *(const float4*)(Vb + (size_t)(kt * 128 + r) * DD + c);
            uint32_t* vp = Vs + r * QPAD + c;
            vp[0] = f2tf(vv.x); vp[1] = f2tf(vv.y); vp[2] = f2tf(vv.z); vp[3] = f2tf(vv.w);
        }
        __syncthreads();
        float acc[4][4][4] = {};
#pragma unroll
        for (int ks = 0; ks < 8; ks++) {
            int k0 = ks * 8;
            uint32_t a[4][4], bf[4][2];
#pragma unroll
            for (int mi = 0; mi < 4; mi++) {
                int rb = wm * 64 + mi * 16 + g;
                a[mi][0] = Qs[rb * QPAD + k0 + tig];
                a[mi][1] = Qs[(rb + 8) * QPAD + k0 + tig];
                a[mi][2] = Qs[rb * QPAD + k0 + tig + 4];
                a[mi][3] = Qs[(rb + 8) * QPAD + k0 + tig + 4];
            }
#pragma unroll
            for (int ni = 0; ni < 4; ni++) {
                int cb = wn * 32 + ni * 8 + g;
                bf[ni][0] = Ks[cb * QPAD + k0 + tig];
                bf[ni][1] = Ks[cb * QPAD + k0 + tig + 4];
            }
#pragma unroll
            for (int mi = 0; mi < 4; mi++)
#pragma unroll
                for (int ni = 0; ni < 4; ni++)
                    mma8(acc[mi][ni], a[mi], bf[ni]);
        }
        // Normalize, emit P to gmem (final output) and to smem (tf32) for PV.
#pragma unroll
        for (int mi = 0; mi < 4; mi++) {
            int rl = wm * 64 + mi * 16 + g;
            float ri0 = rinv[rl], ri1 = rinv[rl + 8];
#pragma unroll
            for (int ni = 0; ni < 4; ni++) {
                int cl = wn * 32 + ni * 8 + tig * 2;
                float p0 = __expf(acc[mi][ni][0]) * ri0;
                float p1 = __expf(acc[mi][ni][1]) * ri0;
                float p2 = __expf(acc[mi][ni][2]) * ri1;
                float p3 = __expf(acc[mi][ni][3]) * ri1;
                *(float2*)(outP + (size_t)(q0 + rl) * NK + kt * 128 + cl) =
                    make_float2(p0, p1);
                *(float2*)(outP + (size_t)(q0 + rl + 8) * NK + kt * 128 + cl) =
                    make_float2(p2, p3);
                uint32_t* pp = Ps + rl * PPAD + cl;
                pp[0] = f2tf(p0); pp[1] = f2tf(p1);
                uint32_t* pq = Ps + (rl + 8) * PPAD + cl;
                pq[0] = f2tf(p2); pq[1] = f2tf(p3);
            }
        }
        __syncthreads();
        // O += P(128x128) * V(128x64)
#pragma unroll
        for (int ks = 0; ks < 16; ks++) {
            int k0 = ks * 8;
            uint32_t a[2][4], bf[4][2];
#pragma unroll
            for (int mi = 0; mi < 2; mi++) {
                int rb = wm2 * 32 + mi * 16 + g;
                a[mi][0] = Ps[rb * PPAD + k0 + tig];
                a[mi][1] = Ps[(rb + 8) * PPAD + k0 + tig];
                a[mi][2] = Ps[rb * PPAD + k0 + tig + 4];
                a[mi][3] = Ps[(rb + 8) * PPAD + k0 + tig + 4];
            }
#pragma unroll
            for (int ni = 0; ni < 4; ni++) {
                int nb = wn2 * 32 + ni * 8 + g;
                bf[ni][0] = Vs[(k0 + tig) * QPAD + nb];
                bf[ni][1] = Vs[(k0 + tig + 4) * QPAD + nb];
            }
#pragma unroll
            for (int mi = 0; mi < 2; mi++)
#pragma unroll
                for (int ni = 0; ni < 4; ni++)
                    mma8(acc_o[mi][ni], a[mi], bf[ni]);
        }
        __syncthreads();
    }
    // Write O
#pragma unroll
    for (int mi = 0; mi < 2; mi++) {
        int r = q0 + wm2 * 32 + mi * 16 + g;
#pragma unroll
        for (int ni = 0; ni < 4; ni++) {
            int c = wn2 * 32 + ni * 8 + tig * 2;
            float* o0 = O + ((size_t)b * NQ + r) * DD + h * HDIM + c;
            *(float2*)o0 = make_float2(acc_o[mi][ni][0], acc_o[mi][ni][1]);
            float* o1 = O + ((size_t)b * NQ + r + 8) * DD + h * HDIM + c;
            *(float2*)o1 = make_float2(acc_o[mi][ni][2], acc_o[mi][ni][3]);
        }
    }
}

// ---------------------------------------------------------------------------
extern "C" void kernel_launch(void* const* d_in, const int* in_sizes, int n_in,
                              void* d_out, int out_size) {
    const float* q_seq   = (const float*)d_in[0];
    const float* kv_seq  = (const float*)d_in[1];
    const float* Wq      = (const float*)d_in[2];
    const float* bq      = (const float*)d_in[3];
    const float* Wk      = (const float*)d_in[4];
    const float* bk      = (const float*)d_in[5];
    const float* Wv      = (const float*)d_in[6];
    const float* bv      = (const float*)d_in[7];
    const float* Wo      = (const float*)d_in[8];
    const float* bo      = (const float*)d_in[9];
    const float* freqs_q = (const float*)d_in[10];
    const float* freqs_kv= (const float*)d_in[11];

    float* out  = (float*)d_out;
    float* attn = out + (size_t)BB * NQ * DD;

    float *gQ, *gK, *gV, *gO;
    cudaGetSymbolAddress((void**)&gQ, g_Q);
    cudaGetSymbolAddress((void**)&gK, g_K);
    cudaGetSymbolAddress((void**)&gV, g_V);
    cudaGetSymbolAddress((void**)&gO, g_O);

    cudaFuncSetAttribute(attn_fused, cudaFuncAttributeMaxDynamicSharedMemorySize,
                         SMEM_BYTES);

    dim3 blk(256);
    dim3 gproj(DD / 128, (BB * NQ) / 128);

    gemm_bias_tc<<<gproj, blk>>>(q_seq,  Wq, bq, gQ, BB * NQ, DD, DD);
    gemm_bias_tc<<<gproj, blk>>>(kv_seq, Wk, bk, gK, BB * NK, DD, DD);
    gemm_bias_tc<<<gproj, blk>>>(kv_seq, Wv, bv, gV, BB * NK, DD, DD);

    int nrope = BB * NQ * HH * (HDIM / 2);
    rope_kernel<<<nrope / 256, 256>>>(gQ, freqs_q,  NQ, (float)(2 * NQ),  1.0f);
    rope_kernel<<<nrope / 256, 256>>>(gK, freqs_kv, NK, (float)(2 * NK), -1.0f);

    attn_fused<<<dim3(NQ / 128, BB * HH), blk, SMEM_BYTES>>>(gQ, gK, gV, attn, gO);

    gemm_bias_tc<<<gproj, blk>>>(gO, Wo, bo, out, BB * NQ, DD, DD);
}

// round 7
// speedup vs baseline: 4.0109x; 1.0887x over previous
#include <cuda_runtime.h>
#include <cuda_bf16.h>
#include <math.h>
#include <stdint.h>

#define BB 2
#define NQ 2048
#define NK 2048
#define DD 1024
#define HH 16
#define HDIM 64

// Scratch (allocation-free: __device__ globals)
__device__ float g_Q[(size_t)BB * NQ * DD];
__device__ float g_K[(size_t)BB * NK * DD];
__device__ float g_V[(size_t)BB * NK * DD];
__device__ float g_O[(size_t)BB * NQ * DD];

// ---------------------------------------------------------------------------
// helpers
// ---------------------------------------------------------------------------
__device__ __forceinline__ uint32_t f2tf(float x) {
    uint32_t y;
    asm("cvt.rna.tf32.f32 %0, %1;" : "=r"(y) : "f"(x));
    return y;
}

__device__ __forceinline__ void mma8(float c[4], const uint32_t a[4], const uint32_t b[2]) {
    asm volatile(
        "mma.sync.aligned.m16n8k8.row.col.f32.tf32.tf32.f32 "
        "{%0,%1,%2,%3}, {%4,%5,%6,%7}, {%8,%9}, {%0,%1,%2,%3};\n"
        : "+f"(c[0]), "+f"(c[1]), "+f"(c[2]), "+f"(c[3])
        : "r"(a[0]), "r"(a[1]), "r"(a[2]), "r"(a[3]), "r"(b[0]), "r"(b[1]));
}

__device__ __forceinline__ void cpa16(uint32_t dst_smem, const void* src) {
    asm volatile("cp.async.cg.shared.global [%0], [%1], 16;\n" :: "r"(dst_smem), "l"(src));
}
__device__ __forceinline__ void cp_commit() {
    asm volatile("cp.async.commit_group;\n");
}
__device__ __forceinline__ void cp_wait0() { asm volatile("cp.async.wait_group 0;\n"); }
__device__ __forceinline__ void cp_wait1() { asm volatile("cp.async.wait_group 1;\n"); }
__device__ __forceinline__ void cp_wait2() { asm volatile("cp.async.wait_group 2;\n"); }

extern __shared__ char smraw[];

// ---------------------------------------------------------------------------
// Tensor-core GEMM + optional fused xpos-RoPE epilogue.
// Y[m][n] = sum_k X[m][k]*W[n][k] + b[n]   (then rope if do_rope!=0)
// 256x128 block tile, k-tile 32, cp.async double buffered. 256 threads,
// 8 warps (4x2), warp tile 64x64. Raw f32 in smem; cvt.rna at fragment load.
// ---------------------------------------------------------------------------
#define GBM 256
#define GBN 128
#define GBK 32
#define GPAD 36
#define GEMM_SMEM ((2 * GBM * GPAD + 2 * GBN * GPAD) * 4)

__global__ void __launch_bounds__(256, 1)
gemm_bias_rope_tc(const float* __restrict__ X, const float* __restrict__ W,
                  const float* __restrict__ bias, float* __restrict__ Y,
                  int M, int N, int K,
                  const float* __restrict__ freqs, float scale_base, float rsign,
                  int do_rope) {
    float* Xs = (float*)smraw;                 // [2][GBM][GPAD]
    float* Ws = Xs + 2 * GBM * GPAD;           // [2][GBN][GPAD]

    int tid = threadIdx.x;
    int warp = tid >> 5, lane = tid & 31;
    int g = lane >> 2, tig = lane & 3;
    int wm = warp >> 1, wn = warp & 1;         // 4 x 2 warps
    int row0 = blockIdx.y * GBM, col0 = blockIdx.x * GBN;

    uint32_t xsB = (uint32_t)__cvta_generic_to_shared(Xs);
    uint32_t wsB = (uint32_t)__cvta_generic_to_shared(Ws);

    float acc[4][8][4] = {};

    // stage tile kt into buffer buf
#define GSTAGE(buf, kt)                                                          \
    do {                                                                         \
        _Pragma("unroll")                                                        \
        for (int i = 0; i < 8; i++) {                                            \
            int idx = tid + i * 256;                                             \
            int r = idx >> 3, c4 = (idx & 7) * 4;                                \
            cpa16(xsB + ((buf) * GBM * GPAD + r * GPAD + c4) * 4,                \
                  X + (size_t)(row0 + r) * K + (kt) + c4);                       \
        }                                                                        \
        _Pragma("unroll")                                                        \
        for (int i = 0; i < 4; i++) {                                            \
            int idx = tid + i * 256;                                             \
            int r = idx >> 3, c4 = (idx & 7) * 4;                                \
            cpa16(wsB + ((buf) * GBN * GPAD + r * GPAD + c4) * 4,                \
                  W + (size_t)(col0 + r) * K + (kt) + c4);                       \
        }                                                                        \
        cp_commit();                                                             \
    } while (0)

    GSTAGE(0, 0);
    int T = K / GBK;
    for (int t = 0; t < T; t++) {
        if (t + 1 < T) { GSTAGE((t + 1) & 1, (t + 1) * GBK); cp_wait1(); }
        else           { cp_wait0(); }
        __syncthreads();
        const float* Xb = Xs + (t & 1) * GBM * GPAD;
        const float* Wb = Ws + (t & 1) * GBN * GPAD;
#pragma unroll
        for (int ks = 0; ks < 4; ks++) {
            int k0 = ks * 8;
            uint32_t a[4][4], bf[8][2];
#pragma unroll
            for (int mi = 0; mi < 4; mi++) {
                int rb = wm * 64 + mi * 16 + g;
                a[mi][0] = f2tf(Xb[rb * GPAD + k0 + tig]);
                a[mi][1] = f2tf(Xb[(rb + 8) * GPAD + k0 + tig]);
                a[mi][2] = f2tf(Xb[rb * GPAD + k0 + tig + 4]);
                a[mi][3] = f2tf(Xb[(rb + 8) * GPAD + k0 + tig + 4]);
            }
#pragma unroll
            for (int ni = 0; ni < 8; ni++) {
                int cb = wn * 64 + ni * 8 + g;
                bf[ni][0] = f2tf(Wb[cb * GPAD + k0 + tig]);
                bf[ni][1] = f2tf(Wb[cb * GPAD + k0 + tig + 4]);
            }
#pragma unroll
            for (int mi = 0; mi < 4; mi++)
#pragma unroll
                for (int ni = 0; ni < 8; ni++)
                    mma8(acc[mi][ni], a[mi], bf[ni]);
        }
        __syncthreads();
    }
#undef GSTAGE

    // Epilogue: bias (+ optional rope), write.
#pragma unroll
    for (int mi = 0; mi < 4; mi++) {
        int r = row0 + wm * 64 + mi * 16 + g;
#pragma unroll
        for (int ni = 0; ni < 8; ni++) {
            int c = col0 + wn * 64 + ni * 8 + tig * 2;
            float v0 = acc[mi][ni][0] + bias[c];
            float v1 = acc[mi][ni][1] + bias[c + 1];
            float v2 = acc[mi][ni][2] + bias[c];
            float v3 = acc[mi][ni][3] + bias[c + 1];
            if (do_rope) {
                int cd = c & (HDIM - 1);           // even in [0,64)
                float f = freqs[cd >> 1];
                float sv = ((float)cd + 0.4f * (float)HDIM) / (1.4f * (float)HDIM);
                // pair 0: row r
                {
                    float n0 = (float)(r & (NQ - 1));
                    float sn, cs; sincosf(n0 * f, &sn, &cs);
                    float scale = powf(sv, (n0 - (float)(NQ / 2)) / scale_base * rsign);
                    float o0 = (v0 * cs - v1 * sn) * scale;
                    float o1 = (v1 * cs + v0 * sn) * scale;
                    v0 = o0; v1 = o1;
                }
                // pair 1: row r+8
                {
                    float n1 = (float)((r + 8) & (NQ - 1));
                    float sn, cs; sincosf(n1 * f, &sn, &cs);
                    float scale = powf(sv, (n1 - (float)(NQ / 2)) / scale_base * rsign);
                    float o2 = (v2 * cs - v3 * sn) * scale;
                    float o3 = (v3 * cs + v2 * sn) * scale;
                    v2 = o2; v3 = o3;
                }
            }
            *(float2*)(Y + (size_t)r * N + c) = make_float2(v0, v1);
            *(float2*)(Y + (size_t)(r + 8) * N + c) = make_float2(v2, v3);
        }
    }
}

// ---------------------------------------------------------------------------
// Fused attention (two-pass, cp.async pipelined).
// Pass 1: S = (0.125*Q)K^T, accumulate row sums of exp(S).
// Pass 2: recompute S (bit-identical), P=exp(S)*rinv -> gmem + smem(tf32),
//         O += P*V (tensor cores). K double-buffered; V prefetched one
//         phase ahead via split cp.async groups.
// ---------------------------------------------------------------------------
#define APAD 68
#define PPAD 132
#define OQ_W 0
#define OK_W (128 * APAD)
#define OV_W (OK_W + 2 * 128 * APAD)
#define OP_W (OV_W + 128 * APAD)
#define OPART_W (OP_W + 128 * PPAD)
#define ORINV_W (OPART_W + 512)
#define ATTN_SMEM ((ORINV_W + 128) * 4)

__global__ void __launch_bounds__(256, 1)
attn_fused(const float* __restrict__ Q, const float* __restrict__ Kg,
           const float* __restrict__ Vg, float* __restrict__ attn,
           float* __restrict__ O) {
    uint32_t* smw = (uint32_t*)smraw;
    uint32_t* Qs = smw + OQ_W;              // [128][APAD] tf32
    float* Ks = (float*)(smw + OK_W);       // [2][128][APAD] raw f32
    float* Vs = (float*)(smw + OV_W);       // [128][APAD] raw f32
    uint32_t* Ps = smw + OP_W;              // [128][PPAD] tf32
    float* part = (float*)(smw + OPART_W);  // [4][128]
    float* rinv = (float*)(smw + ORINV_W);  // [128]

    int bh = blockIdx.y;
    int b = bh / HH, h = bh % HH;
    int q0 = blockIdx.x * 128;
    const float* Qb = Q + (size_t)b * NQ * DD + h * HDIM;
    const float* Kb = Kg + (size_t)b * NK * DD + h * HDIM;
    const float* Vb = Vg + (size_t)b * NK * DD + h * HDIM;
    float* outP = attn + (size_t)bh * NQ * NK;

    int tid = threadIdx.x;
    int warp = tid >> 5, lane = tid & 31;
    int g = lane >> 2, tig = lane & 3;
    int wm = warp >> 2, wn = warp & 3;      // 2x4 (S)
    int wm2 = warp >> 1, wn2 = warp & 1;    // 4x2 (PV)

    uint32_t ksB = (uint32_t)__cvta_generic_to_shared(Ks);
    uint32_t vsB = (uint32_t)__cvta_generic_to_shared(Vs);

#define KSTAGE(buf, kt)                                                          \
    do {                                                                         \
        _Pragma("unroll")                                                        \
        for (int i = 0; i < 8; i++) {                                            \
            int idx = tid + i * 256;                                             \
            int r = idx >> 4, c4 = (idx & 15) * 4;                               \
            cpa16(ksB + ((buf) * 128 * APAD + r * APAD + c4) * 4,                \
                  Kb + (size_t)((kt) * 128 + r) * DD + c4);                      \
        }                                                                        \
        cp_commit();                                                             \
    } while (0)

#define VSTAGE(kt)                                                               \
    do {                                                                         \
        _Pragma("unroll")                                                        \
        for (int i = 0; i < 8; i++) {                                            \
            int idx = tid + i * 256;                                             \
            int r = idx >> 4, c4 = (idx & 15) * 4;                               \
            cpa16(vsB + (r * APAD + c4) * 4,                                     \
                  Vb + (size_t)((kt) * 128 + r) * DD + c4);                      \
        }                                                                        \
        cp_commit();                                                             \
    } while (0)

    // Load Q tile once, pre-scaled by HD^-0.5 = 0.125.
#pragma unroll
    for (int i = 0; i < 8; i++) {
        int idx = tid + i * 256;
        int r = idx >> 4, c = (idx & 15) * 4;
        float4 v = *(const float4*)(Qb + (size_t)(q0 + r) * DD + c);
        uint32_t* p = Qs + r * APAD + c;
        p[0] = f2tf(v.x * 0.125f); p[1] = f2tf(v.y * 0.125f);
        p[2] = f2tf(v.z * 0.125f); p[3] = f2tf(v.w * 0.125f);
    }

    // ---------------- Pass 1: row sums of exp(S) ----------------
    float rs[8] = {};
    KSTAGE(0, 0);
    for (int kt = 0; kt < 16; kt++) {
        if (kt < 15) { KSTAGE((kt + 1) & 1, kt + 1); cp_wait1(); }
        else         { cp_wait0(); }
        __syncthreads();
        const float* Kbs = Ks + (kt & 1) * 128 * APAD;
        float acc[4][4][4] = {};
#pragma unroll
        for (int ks = 0; ks < 8; ks++) {
            int k0 = ks * 8;
            uint32_t a[4][4], bf[4][2];
#pragma unroll
            for (int mi = 0; mi < 4; mi++) {
                int rb = wm * 64 + mi * 16 + g;
                a[mi][0] = Qs[rb * APAD + k0 + tig];
                a[mi][1] = Qs[(rb + 8) * APAD + k0 + tig];
                a[mi][2] = Qs[rb * APAD + k0 + tig + 4];
                a[mi][3] = Qs[(rb + 8) * APAD + k0 + tig + 4];
            }
#pragma unroll
            for (int ni = 0; ni < 4; ni++) {
                int cb = wn * 32 + ni * 8 + g;
                bf[ni][0] = f2tf(Kbs[cb * APAD + k0 + tig]);
                bf[ni][1] = f2tf(Kbs[cb * APAD + k0 + tig + 4]);
            }
#pragma unroll
            for (int mi = 0; mi < 4; mi++)
#pragma unroll
                for (int ni = 0; ni < 4; ni++)
                    mma8(acc[mi][ni], a[mi], bf[ni]);
        }
#pragma unroll
        for (int mi = 0; mi < 4; mi++)
#pragma unroll
            for (int ni = 0; ni < 4; ni++) {
                rs[mi * 2 + 0] += __expf(acc[mi][ni][0]) + __expf(acc[mi][ni][1]);
                rs[mi * 2 + 1] += __expf(acc[mi][ni][2]) + __expf(acc[mi][ni][3]);
            }
        __syncthreads();
    }
    // Deterministic cross-warp row-sum reduction.
#pragma unroll
    for (int j = 0; j < 8; j++) {
        float v = rs[j];
        v += __shfl_xor_sync(0xffffffffu, v, 1);
        v += __shfl_xor_sync(0xffffffffu, v, 2);
        if (tig == 0)
            part[wn * 128 + wm * 64 + (j >> 1) * 16 + g + (j & 1) * 8] = v;
    }
    __syncthreads();
    if (tid < 128)
        rinv[tid] = 1.0f / (part[tid] + part[128 + tid] + part[256 + tid] + part[384 + tid]);
    __syncthreads();

    // ---------------- Pass 2: P out + P*V ----------------
    float acc_o[2][4][4] = {};
    KSTAGE(0, 0);
    for (int kt = 0; kt < 16; kt++) {
        if (kt < 15) KSTAGE((kt + 1) & 1, kt + 1);
        VSTAGE(kt);
        if (kt < 15) cp_wait2(); else cp_wait1();   // K(kt) ready
        __syncthreads();
        const float* Kbs = Ks + (kt & 1) * 128 * APAD;
        float acc[4][4][4] = {};
#pragma unroll
        for (int ks = 0; ks < 8; ks++) {
            int k0 = ks * 8;
            uint32_t a[4][4], bf[4][2];
#pragma unroll
            for (int mi = 0; mi < 4; mi++) {
                int rb = wm * 64 + mi * 16 + g;
                a[mi][0] = Qs[rb * APAD + k0 + tig];
                a[mi][1] = Qs[(rb + 8) * APAD + k0 + tig];
                a[mi][2] = Qs[rb * APAD + k0 + tig + 4];
                a[mi][3] = Qs[(rb + 8) * APAD + k0 + tig + 4];
            }
#pragma unroll
            for (int ni = 0; ni < 4; ni++) {
                int cb = wn * 32 + ni * 8 + g;
                bf[ni][0] = f2tf(Kbs[cb * APAD + k0 + tig]);
                bf[ni][1] = f2tf(Kbs[cb * APAD + k0 + tig + 4]);
            }
#pragma unroll
            for (int mi = 0; mi < 4; mi++)
#pragma unroll
                for (int ni = 0; ni < 4; ni++)
                    mma8(acc[mi][ni], a[mi], bf[ni]);
        }
        // Normalize, emit P to gmem and smem (tf32).
#pragma unroll
        for (int mi = 0; mi < 4; mi++) {
            int rl = wm * 64 + mi * 16 + g;
            float ri0 = rinv[rl], ri1 = rinv[rl + 8];
#pragma unroll
            for (int ni = 0; ni < 4; ni++) {
                int cl = wn * 32 + ni * 8 + tig * 2;
                float p0 = __expf(acc[mi][ni][0]) * ri0;
                float p1 = __expf(acc[mi][ni][1]) * ri0;
                float p2 = __expf(acc[mi][ni][2]) * ri1;
                float p3 = __expf(acc[mi][ni][3]) * ri1;
                *(float2*)(outP + (size_t)(q0 + rl) * NK + kt * 128 + cl) =
                    make_float2(p0, p1);
                *(float2*)(outP + (size_t)(q0 + rl + 8) * NK + kt * 128 + cl) =
                    make_float2(p2, p3);
                uint32_t* pp = Ps + rl * PPAD + cl;
                pp[0] = f2tf(p0); pp[1] = f2tf(p1);
                uint32_t* pq = Ps + (rl + 8) * PPAD + cl;
                pq[0] = f2tf(p2); pq[1] = f2tf(p3);
            }
        }
        if (kt < 15) cp_wait1(); else cp_wait0();   // V(kt) ready
        __syncthreads();                            // Ps + Vs visible
        // O += P(128x128) * V(128x64)
#pragma unroll
        for (int ks = 0; ks < 16; ks++) {
            int k0 = ks * 8;
            uint32_t a[2][4], bf[4][2];
#pragma unroll
            for (int mi = 0; mi < 2; mi++) {
                int rb = wm2 * 32 + mi * 16 + g;
                a[mi][0] = Ps[rb * PPAD + k0 + tig];
                a[mi][1] = Ps[(rb + 8) * PPAD + k0 + tig];
                a[mi][2] = Ps[rb * PPAD + k0 + tig + 4];
                a[mi][3] = Ps[(rb + 8) * PPAD + k0 + tig + 4];
            }
#pragma unroll
            for (int ni = 0; ni < 4; ni++) {
                int nb = wn2 * 32 + ni * 8 + g;
                bf[ni][0] = f2tf(Vs[(k0 + tig) * APAD + nb]);
                bf[ni][1] = f2tf(Vs[(k0 + tig + 4) * APAD + nb]);
            }
#pragma unroll
            for (int mi = 0; mi < 2; mi++)
#pragma unroll
                for (int ni = 0; ni < 4; ni++)
                    mma8(acc_o[mi][ni], a[mi], bf[ni]);
        }
        __syncthreads();
    }
#undef KSTAGE
#undef VSTAGE

    // Write O
#pragma unroll
    for (int mi = 0; mi < 2; mi++) {
        int r = q0 + wm2 * 32 + mi * 16 + g;
#pragma unroll
        for (int ni = 0; ni < 4; ni++) {
            int c = wn2 * 32 + ni * 8 + tig * 2;
            float* o0 = O + ((size_t)b * NQ + r) * DD + h * HDIM + c;
            *(float2*)o0 = make_float2(acc_o[mi][ni][0], acc_o[mi][ni][1]);
            float* o1 = O + ((size_t)b * NQ + r + 8) * DD + h * HDIM + c;
            *(float2*)o1 = make_float2(acc_o[mi][ni][2], acc_o[mi][ni][3]);
        }
    }
}

// ---------------------------------------------------------------------------
extern "C" void kernel_launch(void* const* d_in, const int* in_sizes, int n_in,
                              void* d_out, int out_size) {
    const float* q_seq   = (const float*)d_in[0];
    const float* kv_seq  = (const float*)d_in[1];
    const float* Wq      = (const float*)d_in[2];
    const float* bq      = (const float*)d_in[3];
    const float* Wk      = (const float*)d_in[4];
    const float* bk      = (const float*)d_in[5];
    const float* Wv      = (const float*)d_in[6];
    const float* bv      = (const float*)d_in[7];
    const float* Wo      = (const float*)d_in[8];
    const float* bo      = (const float*)d_in[9];
    const float* freqs_q = (const float*)d_in[10];
    const float* freqs_kv= (const float*)d_in[11];

    float* out  = (float*)d_out;
    float* attn = out + (size_t)BB * NQ * DD;

    float *gQ, *gK, *gV, *gO;
    cudaGetSymbolAddress((void**)&gQ, g_Q);
    cudaGetSymbolAddress((void**)&gK, g_K);
    cudaGetSymbolAddress((void**)&gV, g_V);
    cudaGetSymbolAddress((void**)&gO, g_O);

    static int attr_done = 0;
    if (!attr_done) {
        cudaFuncSetAttribute(gemm_bias_rope_tc,
                             cudaFuncAttributeMaxDynamicSharedMemorySize, GEMM_SMEM);
        cudaFuncSetAttribute(attn_fused,
                             cudaFuncAttributeMaxDynamicSharedMemorySize, ATTN_SMEM);
        attr_done = 1;
    }

    dim3 blk(256);
    dim3 gproj(DD / GBN, (BB * NQ) / GBM);   // 8 x 16 = 128 blocks

    gemm_bias_rope_tc<<<gproj, blk, GEMM_SMEM>>>(
        q_seq, Wq, bq, gQ, BB * NQ, DD, DD, freqs_q, (float)(2 * NQ), 1.0f, 1);
    gemm_bias_rope_tc<<<gproj, blk, GEMM_SMEM>>>(
        kv_seq, Wk, bk, gK, BB * NK, DD, DD, freqs_kv, (float)(2 * NK), -1.0f, 1);
    gemm_bias_rope_tc<<<gproj, blk, GEMM_SMEM>>>(
        kv_seq, Wv, bv, gV, BB * NK, DD, DD, nullptr, 1.0f, 0.0f, 0);

    attn_fused<<<dim3(NQ / 128, BB * HH), blk, ATTN_SMEM>>>(gQ, gK, gV, attn, gO);

    gemm_bias_rope_tc<<<gproj, blk, GEMM_SMEM>>>(
        gO, Wo, bo, out, BB * NQ, DD, DD, nullptr, 1.0f, 0.0f, 0);
}